// round 2
// baseline (speedup 1.0000x reference)
#include <cuda_runtime.h>
#include <cuda_bf16.h>

// Problem: x [3,5,32,64,32,32] binary float. Per 32x32 image: connected
// components (4-neighbor) of foreground; result = max over bincount of labels
// (background label 0 included) = max(#bg, largest fg component).
// Then per (C,B,Bt): (sum over 64 patches) // 64, as float. Output 480 floats.

#define N_IMG 30720
#define N_OUT 480

__device__ int g_acc[N_OUT];

__global__ void zero_acc_kernel() {
    int i = threadIdx.x;
    if (i < N_OUT) g_acc[i] = 0;
}

__device__ __forceinline__ int find_root(const int* Lp, int i) {
    volatile const int* L = Lp;
    int p = L[i];
    while (p != i) { i = p; p = L[i]; }
    return i;
}

__device__ __forceinline__ void unite(int* L, int a, int b) {
    while (true) {
        a = find_root(L, a);
        b = find_root(L, b);
        if (a == b) return;
        int mn = min(a, b);
        int mx = max(a, b);
        int old = atomicMin(&L[mx], mn);
        if (old == mx) return;   // successfully linked
        a = old; b = mn;         // someone else relinked mx; retry
    }
}

// start column of the run of 1s containing bit c in mask m (bit c must be set)
__device__ __forceinline__ int run_start(unsigned m, int c) {
    unsigned zb = (~m) & ((1u << c) - 1u);   // zeros strictly below c
    return zb ? (32 - __clz(zb)) : 0;
}

__global__ void __launch_bounds__(256)
ccl_kernel(const float4* __restrict__ x) {
    __shared__ int L[1024];
    __shared__ int cnt[1024];
    __shared__ unsigned mask[32];
    __shared__ int s_max;
    __shared__ int s_fg;

    const int img = blockIdx.x;
    const int t   = threadIdx.x;

    if (t == 0) { s_max = 0; s_fg = 0; }

    // ---- load 4 pixels (one float4, coalesced) and build row bitmasks ----
    float4 v = x[(size_t)img * 256 + t];
    unsigned nib = (unsigned)(v.x != 0.0f)
                 | ((unsigned)(v.y != 0.0f) << 1)
                 | ((unsigned)(v.z != 0.0f) << 2)
                 | ((unsigned)(v.w != 0.0f) << 3);
    // thread t owns pixels [4t, 4t+3]: row r = t>>3, col base = (t&7)*4
    const int r    = t >> 3;
    const int cbit = (t & 7) * 4;
    unsigned part = nib << cbit;
    part |= __shfl_xor_sync(0xffffffffu, part, 1);
    part |= __shfl_xor_sync(0xffffffffu, part, 2);
    part |= __shfl_xor_sync(0xffffffffu, part, 4);
    if ((t & 7) == 0) mask[r] = part;

    // init union-find labels + counts
#pragma unroll
    for (int k = 0; k < 4; k++) {
        int i = t + 256 * k;
        L[i] = i;
        cnt[i] = 0;
    }
    __syncthreads();

    const unsigned m_r = mask[r];

    // ---- vertical unions between row r and r+1, only at overlap-run starts ----
    if (r < 31) {
        const unsigned m_d = mask[r + 1];
        unsigned ov = m_r & m_d;
        unsigned st = ov & ~(ov << 1);          // start bits of overlap runs
        st = (st >> cbit) & 0xFu;               // this thread's 4-bit slice
        while (st) {
            int c = cbit + (__ffs(st) - 1);
            st &= st - 1;
            int a = r * 32 + run_start(m_r, c);
            int b = (r + 1) * 32 + run_start(m_d, c);
            unite(L, a, b);
        }
    }

    // foreground total (warp 0 only)
    if (t < 32) {
        int fgc = __popc(mask[t]);
        fgc = __reduce_add_sync(0xffffffffu, fgc);
        if (t == 0) s_fg = fgc;
    }
    __syncthreads();

    // ---- accumulate run lengths at component roots ----
    {
        unsigned st = m_r & ~(m_r << 1);        // run starts of this row
        st = (st >> cbit) & 0xFu;
        while (st) {
            int c = cbit + (__ffs(st) - 1);
            st &= st - 1;
            unsigned inv = ~(m_r >> c);
            int len = inv ? (__ffs(inv) - 1) : 32;
            int root = find_root(L, r * 32 + c);
            atomicAdd(&cnt[root], len);
        }
    }
    __syncthreads();

    // ---- block max over component counts ----
    int mx = 0;
#pragma unroll
    for (int k = 0; k < 4; k++) mx = max(mx, cnt[t + 256 * k]);
    mx = __reduce_max_sync(0xffffffffu, mx);
    if ((t & 31) == 0) atomicMax(&s_max, mx);
    __syncthreads();

    if (t == 0) {
        int res = max(s_max, 1024 - s_fg);      // include background label 0
        atomicAdd(&g_acc[img >> 6], res);       // 64 patches per output cell
    }
}

__global__ void finalize_kernel(float* __restrict__ out) {
    int i = threadIdx.x;
    if (i < N_OUT) out[i] = (float)(g_acc[i] >> 6);   // integer mean (truncating)
}

extern "C" void kernel_launch(void* const* d_in, const int* in_sizes, int n_in,
                              void* d_out, int out_size) {
    const float4* x = (const float4*)d_in[0];
    float* out = (float*)d_out;
    zero_acc_kernel<<<1, N_OUT>>>();
    ccl_kernel<<<N_IMG, 256>>>(x);
    finalize_kernel<<<1, N_OUT>>>(out);
}

// round 5
// speedup vs baseline: 1.8825x; 1.8825x over previous
#include <cuda_runtime.h>
#include <cuda_bf16.h>

// x: [3,5,32,64,32,32] binary float. Per 32x32 image (4-connectivity):
// result = max(#background, largest foreground component).
// Output[C,B,Bt] = (sum over 64 patches) // 64 as float. 480 outputs.

#define N_IMG 30720
#define IMGS_PER_BLK 8
#define N_OUT 480

__device__ int g_acc[N_OUT];   // zero-init at load; finalize resets after read

__device__ __forceinline__ int uf_find(int* Lp, int i) {
    volatile int* L = Lp;
    int p = L[i];
    if (p == i) return i;
    while (true) {
        int gp = L[p];
        if (gp == p) return p;
        L[i] = gp;          // path halving (plain store: always writes an ancestor)
        i = p; p = gp;
    }
}

__device__ __forceinline__ void uf_union(int* L, int a, int b) {
    while (true) {
        a = uf_find(L, a);
        b = uf_find(L, b);
        if (a == b) return;
        int mn = min(a, b);
        int mx = max(a, b);
        int old = atomicMin(&L[mx], mn);
        if (old == mx) return;
        a = old; b = mn;
    }
}

__global__ void __launch_bounds__(256)
ccl_kernel(const float4* __restrict__ x) {
    // per-warp union-find arrays: nodes are runs, id = k*32 + row (k<16)
    __shared__ int Ls[IMGS_PER_BLK][512];
    __shared__ int Cs[IMGS_PER_BLK][512];

    const int lane = threadIdx.x & 31;
    const int w    = threadIdx.x >> 5;
    const int img  = blockIdx.x * IMGS_PER_BLK + w;
    int* L = Ls[w];
    int* C = Cs[w];

    // ---- coalesced load + in-warp transpose: lane r ends with row-r bitmask ----
    const float4* p = x + (size_t)img * 256;
    unsigned m = 0;
#pragma unroll
    for (int i = 0; i < 8; i++) {
        float4 v = p[i * 32 + lane];                      // 512B contiguous per LDG
        unsigned nib = (unsigned)(v.x != 0.0f)
                     | ((unsigned)(v.y != 0.0f) << 1)
                     | ((unsigned)(v.z != 0.0f) << 2)
                     | ((unsigned)(v.w != 0.0f) << 3);
        unsigned part = nib << ((lane & 7) * 4);          // group g=lane>>3 builds row 4i+g
        part |= __shfl_xor_sync(~0u, part, 1);
        part |= __shfl_xor_sync(~0u, part, 2);
        part |= __shfl_xor_sync(~0u, part, 4);
        unsigned got = __shfl_sync(~0u, part, (lane & 3) * 8);
        if ((lane >> 2) == i) m = got;                    // row r arrives at iter r>>2
    }

    // ---- run decomposition of this row ----
    const unsigned s = m & ~(m << 1);                     // run-start bits
    const int nr = __popc(s);

    // init only the real runs: node id = k*32 + lane (bank-conflict-free)
    for (int k = 0; k < nr; k++) {
        L[k * 32 + lane] = k * 32 + lane;
        C[k * 32 + lane] = 0;
    }
    __syncwarp();

    // ---- vertical unions with row below, one per overlap-run ----
    unsigned m_d = __shfl_down_sync(~0u, m, 1);
    unsigned s_d = __shfl_down_sync(~0u, s, 1);
    if (lane < 31) {
        unsigned ov = m & m_d;
        unsigned st = ov & ~(ov << 1);
        while (st) {
            int c = __ffs(st) - 1;
            st &= st - 1;
            unsigned thr = (2u << c) - 1u;                // bits 0..c (c=31 -> all ones)
            int kr = __popc(s   & thr) - 1;               // run idx in row r
            int kd = __popc(s_d & thr) - 1;               // run idx in row r+1
            uf_union(L, kr * 32 + lane, kd * 32 + lane + 1);
        }
    }
    __syncwarp();

    // ---- accumulate run lengths at roots ----
    {
        unsigned st = s;
        int k = 0;
        while (st) {
            int c = __ffs(st) - 1;
            st &= st - 1;
            unsigned inv = ~(m >> c);
            int len = inv ? (__ffs(inv) - 1) : 32;        // trailing-ones of m>>c
            int root = uf_find(L, k * 32 + lane);
            atomicAdd(&C[root], len);
            k++;
        }
    }
    __syncwarp();

    // ---- per-image result ----
    int mymax = 0;
    for (int k = 0; k < nr; k++) mymax = max(mymax, C[k * 32 + lane]);
    mymax = __reduce_max_sync(~0u, mymax);
    int fg = __reduce_add_sync(~0u, __popc(m));
    if (lane == 0) {
        int res = max(mymax, 1024 - fg);                  // label 0 (background) included
        atomicAdd(&g_acc[img >> 6], res);                 // 64 patches per output cell
    }
}

__global__ void finalize_kernel(float* __restrict__ out) {
    int i = threadIdx.x;
    if (i < N_OUT) {
        out[i] = (float)(g_acc[i] >> 6);                  // truncating integer mean
        g_acc[i] = 0;                                     // reset for next replay
    }
}

extern "C" void kernel_launch(void* const* d_in, const int* in_sizes, int n_in,
                              void* d_out, int out_size) {
    const float4* x = (const float4*)d_in[0];
    float* out = (float*)d_out;
    ccl_kernel<<<N_IMG / IMGS_PER_BLK, 256>>>(x);
    finalize_kernel<<<1, N_OUT>>>(out);
}

// round 7
// speedup vs baseline: 2.2638x; 1.2025x over previous
#include <cuda_runtime.h>
#include <cuda_bf16.h>

// x: [3,5,32,64,32,32] binary float. Per 32x32 image (4-connectivity):
// result = max(#background, largest foreground component).
// Output[C,B,Bt] = (sum over 64 patches) // 64 as float. 480 outputs.
//
// Exact shortcut: largest_fg_comp <= fg, so if fg <= 512 then
// result = 1024 - fg (background wins) and no CCL is needed (~50% of images).
//
// Union-find nodes are row-runs, id = k*32 + row (k < 16, so id < 512).
// After flattening, component sizes accumulate in bits >=10 of L[root];
// the root index always stays in bits [0,10) => mask with 1023 when reading.

#define N_IMG 30720
#define IMGS_PER_BLK 8
#define N_OUT 480

__device__ int g_acc[N_OUT];   // zero-init at load; finalize resets after read

__device__ __forceinline__ int uf_find(int* Lp, int i) {
    volatile int* L = Lp;
    int p = L[i];
    if (p == i) return i;
    while (true) {
        int gp = L[p];
        if (gp == p) return p;
        L[i] = gp;          // path halving (always stores a valid ancestor)
        i = p; p = gp;
    }
}

__device__ __forceinline__ void uf_union(int* L, int a, int b) {
    while (true) {
        a = uf_find(L, a);
        b = uf_find(L, b);
        if (a == b) return;
        int mn = min(a, b);
        int mx = max(a, b);
        int old = atomicMin(&L[mx], mn);
        if (old == mx) return;
        a = old; b = mn;
    }
}

__global__ void __launch_bounds__(256)
ccl_kernel(const float4* __restrict__ x) {
    __shared__ int Ls[IMGS_PER_BLK][512];

    const int lane = threadIdx.x & 31;
    const int w    = threadIdx.x >> 5;
    const int img  = blockIdx.x * IMGS_PER_BLK + w;
    int* L = Ls[w];

    // ---- coalesced load + in-warp transpose: lane r ends with row-r bitmask ----
    const float4* p = x + (size_t)img * 256;
    unsigned m = 0;
#pragma unroll
    for (int i = 0; i < 8; i++) {
        float4 v = p[i * 32 + lane];                      // 512B contiguous per LDG
        unsigned nib = (unsigned)(v.x != 0.0f)
                     | ((unsigned)(v.y != 0.0f) << 1)
                     | ((unsigned)(v.z != 0.0f) << 2)
                     | ((unsigned)(v.w != 0.0f) << 3);
        unsigned part = nib << ((lane & 7) * 4);          // group g=lane>>3 builds row 4i+g
        part |= __shfl_xor_sync(~0u, part, 1);
        part |= __shfl_xor_sync(~0u, part, 2);
        part |= __shfl_xor_sync(~0u, part, 4);
        unsigned got = __shfl_sync(~0u, part, (lane & 3) * 8);
        if ((lane >> 2) == i) m = got;                    // row r arrives at iter r>>2
    }

    const int fg = __reduce_add_sync(~0u, __popc(m));
    int res = 1024 - fg;                                  // background count

    if (fg > 512) {
        // largest fg component could exceed bg: run the CCL.
        const unsigned s = m & ~(m << 1);                 // run-start bits
        const int nr = __popc(s);

        // init only real runs: node id = k*32 + lane (bank-conflict-free)
        for (int k = 0; k < nr; k++)
            L[k * 32 + lane] = k * 32 + lane;
        __syncwarp();

        // ---- vertical unions with row below, one per overlap-run ----
        unsigned m_d = __shfl_down_sync(~0u, m, 1);
        unsigned s_d = __shfl_down_sync(~0u, s, 1);
        if (lane < 31) {
            unsigned ov = m & m_d;
            unsigned st = ov & ~(ov << 1);
            while (st) {
                int c = __ffs(st) - 1;
                st &= st - 1;
                unsigned thr = (2u << c) - 1u;            // bits 0..c
                int kr = __popc(s   & thr) - 1;           // run idx in row r
                int kd = __popc(s_d & thr) - 1;           // run idx in row r+1
                uf_union(L, kr * 32 + lane, kd * 32 + lane + 1);
            }
        }
        __syncwarp();

        // ---- phase A: fully flatten every run to its root (plain stores) ----
        for (int k = 0; k < nr; k++) {
            int id = k * 32 + lane;
            int r  = uf_find(L, id);
            if (r != id) L[id] = r;
        }
        __syncwarp();

        // ---- phase B: accumulate run lengths into bits >=10 of L[root].
        // Root index read must mask off any counts already added (race-safe:
        // adds only touch bits >=10, root index < 512 lives in bits <10).
        {
            unsigned st = s;
            int k = 0;
            while (st) {
                int c = __ffs(st) - 1;
                st &= st - 1;
                unsigned inv = ~(m >> c);
                int len = inv ? (__ffs(inv) - 1) : 32;    // trailing-ones of m>>c
                int id = k * 32 + lane;
                int root = L[id] & 1023;                  // pure root index
                atomicAdd(&L[root], len << 10);
                k++;
            }
        }
        __syncwarp();

        // ---- max component size: roots carry count in bits >=10 ----
        int mymax = 0;
        for (int k = 0; k < nr; k++)
            mymax = max(mymax, L[k * 32 + lane] >> 10);   // non-roots -> 0 (value < 512)
        mymax = __reduce_max_sync(~0u, mymax);
        res = max(mymax, res);
    }

    if (lane == 0)
        atomicAdd(&g_acc[img >> 6], res);                 // 64 patches per output cell
}

__global__ void finalize_kernel(float* __restrict__ out) {
    int i = threadIdx.x;
    if (i < N_OUT) {
        out[i] = (float)(g_acc[i] >> 6);                  // truncating integer mean
        g_acc[i] = 0;                                     // reset for next graph replay
    }
}

extern "C" void kernel_launch(void* const* d_in, const int* in_sizes, int n_in,
                              void* d_out, int out_size) {
    const float4* x = (const float4*)d_in[0];
    float* out = (float*)d_out;
    ccl_kernel<<<N_IMG / IMGS_PER_BLK, 256>>>(x);
    finalize_kernel<<<1, N_OUT>>>(out);
}

// round 10
// speedup vs baseline: 3.4332x; 1.5166x over previous
#include <cuda_runtime.h>
#include <cuda_bf16.h>

// x: [3,5,32,64,32,32] binary float. Per 32x32 image (4-connectivity):
// result = max(#background, largest foreground component).
// Output[C,B,Bt] = (sum over 64 patches) // 64 as float. 480 outputs.
//
// Exact skip: components of size<=2 can't win (bg ~ 500). Isolated pixels and
// isolated dominoes are size<=2 components, so for any component of size>=3:
//   largest <= fg - n_iso - 2*(n_hdom + n_vdom)  (=: fg - excl)
// If fg - excl <= 1024 - fg  =>  result = 1024 - fg, no CCL (~85-90% of images).

#define N_IMG 30720
#define IMGS_PER_BLK 8
#define N_BLK (N_IMG / IMGS_PER_BLK)
#define N_OUT 480

__device__ int g_acc[N_OUT];   // zero-init at load; last block resets after read
__device__ int g_cnt;          // completion ticket; reset each launch

__device__ __forceinline__ int uf_find(int* Lp, int i) {
    volatile int* L = Lp;
    int p = L[i];
    if (p == i) return i;
    while (true) {
        int gp = L[p];
        if (gp == p) return p;
        L[i] = gp;          // path halving (always stores a valid ancestor)
        i = p; p = gp;
    }
}

__device__ __forceinline__ void uf_union(int* L, int a, int b) {
    while (true) {
        a = uf_find(L, a);
        b = uf_find(L, b);
        if (a == b) return;
        int mn = min(a, b);
        int mx = max(a, b);
        int old = atomicMin(&L[mx], mn);
        if (old == mx) return;
        a = old; b = mn;
    }
}

__global__ void __launch_bounds__(256)
ccl_kernel(const float4* __restrict__ x, float* __restrict__ out) {
    __shared__ int Ls[IMGS_PER_BLK][512];
    __shared__ int s_last;

    const int lane = threadIdx.x & 31;
    const int w    = threadIdx.x >> 5;
    const int img  = blockIdx.x * IMGS_PER_BLK + w;
    int* L = Ls[w];

    // ---- coalesced load + in-warp transpose: lane r ends with row-r bitmask ----
    const float4* p = x + (size_t)img * 256;
    unsigned m = 0;
#pragma unroll
    for (int i = 0; i < 8; i++) {
        float4 v = p[i * 32 + lane];                      // 512B contiguous per LDG
        unsigned nib = (unsigned)(v.x != 0.0f)
                     | ((unsigned)(v.y != 0.0f) << 1)
                     | ((unsigned)(v.z != 0.0f) << 2)
                     | ((unsigned)(v.w != 0.0f) << 3);
        unsigned part = nib << ((lane & 7) * 4);          // group g=lane>>3 builds row 4i+g
        part |= __shfl_xor_sync(~0u, part, 1);
        part |= __shfl_xor_sync(~0u, part, 2);
        part |= __shfl_xor_sync(~0u, part, 4);
        unsigned got = __shfl_sync(~0u, part, (lane & 3) * 8);
        if ((lane >> 2) == i) m = got;                    // row r arrives at iter r>>2
    }

    // ---- neighbor row masks (0 at image boundary) ----
    unsigned up  = __shfl_up_sync(~0u, m, 1);   if (lane == 0)   up  = 0;
    unsigned dn  = __shfl_down_sync(~0u, m, 1); if (lane == 31)  dn  = 0;
    unsigned dn2 = __shfl_down_sync(~0u, m, 2); if (lane >= 30)  dn2 = 0;

    // ---- size<=2 isolated components (exact) ----
    // left-occupied = m<<1, right-occupied = m>>1
    unsigned iso = m & ~(m << 1) & ~(m >> 1) & ~up & ~dn;
    unsigned hd  = m & (m >> 1) & ~(m << 1) & ~(m >> 2)
                 & ~up & ~(up >> 1) & ~dn & ~(dn >> 1);   // horiz domino at (c,c+1)
    unsigned vd  = m & dn & ~up & ~dn2
                 & ~(m << 1) & ~(m >> 1) & ~(dn << 1) & ~(dn >> 1); // vert domino

    int pk = __popc(m) + ((__popc(iso) + 2 * (__popc(hd) + __popc(vd))) << 11);
    pk = __reduce_add_sync(~0u, pk);
    const int fg   = pk & 2047;
    const int excl = pk >> 11;

    int res = 1024 - fg;                                  // background count

    if (2 * fg > 1024 + excl) {
        // largest fg component might exceed bg: run run-based union-find.
        const unsigned s = m & ~(m << 1);                 // run-start bits
        const int nr = __popc(s);

        // init only real runs: node id = k*32 + lane (bank-conflict-free)
        for (int k = 0; k < nr; k++)
            L[k * 32 + lane] = k * 32 + lane;
        __syncwarp();

        // ---- vertical unions with row below, one per overlap-run ----
        unsigned s_d = __shfl_down_sync(~0u, s, 1);
        if (lane < 31) {
            unsigned ov = m & dn;
            unsigned st = ov & ~(ov << 1);
            while (st) {
                int c = __ffs(st) - 1;
                st &= st - 1;
                unsigned thr = (2u << c) - 1u;            // bits 0..c
                int kr = __popc(s   & thr) - 1;           // run idx in row r
                int kd = __popc(s_d & thr) - 1;           // run idx in row r+1
                uf_union(L, kr * 32 + lane, kd * 32 + lane + 1);
            }
        }
        __syncwarp();

        // ---- phase A: fully flatten every run to its root ----
        for (int k = 0; k < nr; k++) {
            int id = k * 32 + lane;
            int r  = uf_find(L, id);
            if (r != id) L[id] = r;
        }
        __syncwarp();

        // ---- phase B: accumulate run lengths into bits >=10 of L[root].
        // Root index read masks off counts already added (adds touch only
        // bits >=10; root index < 512 lives in bits <10) -> race-safe.
        {
            unsigned st = s;
            int k = 0;
            while (st) {
                int c = __ffs(st) - 1;
                st &= st - 1;
                unsigned inv = ~(m >> c);
                int len = inv ? (__ffs(inv) - 1) : 32;    // trailing-ones of m>>c
                int id = k * 32 + lane;
                int root = L[id] & 1023;                  // pure root index
                atomicAdd(&L[root], len << 10);
                k++;
            }
        }
        __syncwarp();

        // ---- max component size: roots carry count in bits >=10 ----
        int mymax = 0;
        for (int k = 0; k < nr; k++)
            mymax = max(mymax, L[k * 32 + lane] >> 10);   // non-roots -> 0
        mymax = __reduce_max_sync(~0u, mymax);
        res = max(mymax, res);
    }

    if (lane == 0)
        atomicAdd(&g_acc[img >> 6], res);                 // 64 patches per output cell

    // ---- last-block-done: fold finalize into this kernel ----
    __syncthreads();
    if (threadIdx.x == 0) {
        __threadfence();
        int old = atomicAdd(&g_cnt, 1);
        s_last = (old == N_BLK - 1);
    }
    __syncthreads();
    if (s_last) {
        __threadfence();
        for (int i = threadIdx.x; i < N_OUT; i += blockDim.x) {
            int v = __ldcg(&g_acc[i]);                    // L2-coherent read
            out[i] = (float)(v >> 6);                     // truncating integer mean
            __stcg(&g_acc[i], 0);                         // reset for next replay
        }
        if (threadIdx.x == 0) __stcg(&g_cnt, 0);
    }
}

extern "C" void kernel_launch(void* const* d_in, const int* in_sizes, int n_in,
                              void* d_out, int out_size) {
    const float4* x = (const float4*)d_in[0];
    float* out = (float*)d_out;
    ccl_kernel<<<N_BLK, 256>>>(x, out);
}

// round 13
// speedup vs baseline: 4.4913x; 1.3082x over previous
#include <cuda_runtime.h>
#include <cuda_bf16.h>

// x: [3,5,32,64,32,32] binary float. Per 32x32 image (4-connectivity):
// result = max(#background, largest foreground component).
// Output[C,B,Bt] = (sum over 64 patches) // 64 as float. 480 outputs.
//
// Exact skip: size<=2 isolated components (pixels/dominoes) can't be the max;
// if fg - excl <= 1024 - fg  =>  result = 1024 - fg, no CCL (~97% of images).
//
// Row masks built via packed-nibble butterfly transpose (3 shfl_xor) instead of
// 32 dependent shfls. Lane l holds row r = 4*(l&7) + (l>>3).

#define N_IMG 30720
#define IMGS_PER_BLK 4
#define N_BLK (N_IMG / IMGS_PER_BLK)
#define N_OUT 480

__device__ int g_acc[N_OUT];   // zero-init at load; last block resets after read
__device__ int g_cnt;          // completion ticket; reset each launch

__device__ __forceinline__ int uf_find(int* Lp, int i) {
    volatile int* L = Lp;
    int p = L[i];
    if (p == i) return i;
    while (true) {
        int gp = L[p];
        if (gp == p) return p;
        L[i] = gp;          // path halving (always stores a valid ancestor)
        i = p; p = gp;
    }
}

__device__ __forceinline__ void uf_union(int* L, int a, int b) {
    while (true) {
        a = uf_find(L, a);
        b = uf_find(L, b);
        if (a == b) return;
        int mn = min(a, b);
        int mx = max(a, b);
        int old = atomicMin(&L[mx], mn);
        if (old == mx) return;
        a = old; b = mn;
    }
}

__device__ __forceinline__ int lane_of_row(int t) {   // inverse of r = 4*(l&7)+(l>>3)
    return ((t & 3) << 3) + (t >> 2);
}

__global__ void __launch_bounds__(128)
ccl_kernel(const float4* __restrict__ x, float* __restrict__ out) {
    __shared__ int Ls[IMGS_PER_BLK][512];
    __shared__ int s_last;

    const int lane = threadIdx.x & 31;
    const int w    = threadIdx.x >> 5;
    const int img  = blockIdx.x * IMGS_PER_BLK + w;
    int* L = Ls[w];

    // ---- load 8 float4 (independent -> MLP=8, 512B contiguous per LDG) ----
    const float4* p = x + (size_t)img * 256;
    float4 v0 = p[0*32+lane], v1 = p[1*32+lane], v2 = p[2*32+lane], v3 = p[3*32+lane];
    float4 v4 = p[4*32+lane], v5 = p[5*32+lane], v6 = p[6*32+lane], v7 = p[7*32+lane];

    // pack 8 nibbles: values are exactly 0.0/1.0 so nib = x+2y+4z+8w is exact
#define NIB(v) ((unsigned)(int)((v).x + 2.0f*(v).y + 4.0f*(v).z + 8.0f*(v).w))
    unsigned m =  NIB(v0)        | (NIB(v1) << 4)  | (NIB(v2) << 8)  | (NIB(v3) << 12)
               | (NIB(v4) << 16) | (NIB(v5) << 20) | (NIB(v6) << 24) | (NIB(v7) << 28);
#undef NIB
    // lane l, nibble i = (row 4i + (l>>3), cols 4*(l&7)..4*(l&7)+3)

    // ---- 8x8 nibble transpose within each 8-lane group (3 butterfly steps) ----
    {
        unsigned y;
        y = __shfl_xor_sync(~0u, m, 4);
        m = (lane & 4) ? ((m & 0xFFFF0000u) | (y >> 16))
                       : ((m & 0x0000FFFFu) | (y << 16));
        y = __shfl_xor_sync(~0u, m, 2);
        m = (lane & 2) ? ((m & 0xFF00FF00u) | ((y >> 8) & 0x00FF00FFu))
                       : ((m & 0x00FF00FFu) | ((y << 8) & 0xFF00FF00u));
        y = __shfl_xor_sync(~0u, m, 1);
        m = (lane & 1) ? ((m & 0xF0F0F0F0u) | ((y >> 4) & 0x0F0F0F0Fu))
                       : ((m & 0x0F0F0F0Fu) | ((y << 4) & 0xF0F0F0F0u));
    }
    const int r = 4 * (lane & 7) + (lane >> 3);          // row held by this lane

    // ---- neighbor row masks (0 at image boundary); independent shfls ----
    unsigned up  = __shfl_sync(~0u, m, lane_of_row((r - 1) & 31));
    unsigned dn  = __shfl_sync(~0u, m, lane_of_row((r + 1) & 31));
    unsigned dn2 = __shfl_sync(~0u, m, lane_of_row((r + 2) & 31));
    if (r == 0)   up  = 0;
    if (r == 31)  dn  = 0;
    if (r >= 30)  dn2 = 0;

    // ---- size<=2 isolated components (exact) ----
    unsigned iso = m & ~(m << 1) & ~(m >> 1) & ~up & ~dn;
    unsigned hd  = m & (m >> 1) & ~(m << 1) & ~(m >> 2)
                 & ~up & ~(up >> 1) & ~dn & ~(dn >> 1);   // horiz domino
    unsigned vd  = m & dn & ~up & ~dn2
                 & ~(m << 1) & ~(m >> 1) & ~(dn << 1) & ~(dn >> 1); // vert domino

    int pk = __popc(m) + ((__popc(iso) + 2 * (__popc(hd) + __popc(vd))) << 11);
    pk = __reduce_add_sync(~0u, pk);
    const int fg   = pk & 2047;
    const int excl = pk >> 11;

    int res = 1024 - fg;                                  // background count

    if (2 * fg > 1024 + excl) {
        // largest fg component might exceed bg: run-based union-find.
        const unsigned s = m & ~(m << 1);                 // run-start bits
        const int nr = __popc(s);

        // node id = k*32 + r (r is a permutation of lanes -> conflict-free)
        for (int k = 0; k < nr; k++)
            L[k * 32 + r] = k * 32 + r;
        __syncwarp();

        // ---- vertical unions with row r+1, one per overlap-run ----
        unsigned s_d = __shfl_sync(~0u, s, lane_of_row((r + 1) & 31));
        if (r < 31) {
            unsigned ov = m & dn;
            unsigned st = ov & ~(ov << 1);
            while (st) {
                int c = __ffs(st) - 1;
                st &= st - 1;
                unsigned thr = (2u << c) - 1u;            // bits 0..c
                int kr = __popc(s   & thr) - 1;           // run idx in row r
                int kd = __popc(s_d & thr) - 1;           // run idx in row r+1
                uf_union(L, kr * 32 + r, kd * 32 + r + 1);
            }
        }
        __syncwarp();

        // ---- phase A: fully flatten every run to its root ----
        for (int k = 0; k < nr; k++) {
            int id = k * 32 + r;
            int rt = uf_find(L, id);
            if (rt != id) L[id] = rt;
        }
        __syncwarp();

        // ---- phase B: run lengths into bits >=10 of L[root] (mask low 10
        // bits when reading root: adds only touch bits >=10, root idx < 512)
        {
            unsigned st = s;
            int k = 0;
            while (st) {
                int c = __ffs(st) - 1;
                st &= st - 1;
                unsigned inv = ~(m >> c);
                int len = inv ? (__ffs(inv) - 1) : 32;    // trailing-ones of m>>c
                int root = L[k * 32 + r] & 1023;
                atomicAdd(&L[root], len << 10);
                k++;
            }
        }
        __syncwarp();

        // ---- max component size: roots carry count in bits >=10 ----
        int mymax = 0;
        for (int k = 0; k < nr; k++)
            mymax = max(mymax, L[k * 32 + r] >> 10);      // non-roots -> 0
        mymax = __reduce_max_sync(~0u, mymax);
        res = max(mymax, res);
    }

    if (lane == 0)
        atomicAdd(&g_acc[img >> 6], res);                 // 64 patches per output cell

    // ---- last-block-done: fold finalize into this kernel ----
    __syncthreads();
    if (threadIdx.x == 0) {
        __threadfence();
        int old = atomicAdd(&g_cnt, 1);
        s_last = (old == N_BLK - 1);
    }
    __syncthreads();
    if (s_last) {
        __threadfence();
        for (int i = threadIdx.x; i < N_OUT; i += blockDim.x) {
            int vv = __ldcg(&g_acc[i]);                   // L2-coherent read
            out[i] = (float)(vv >> 6);                    // truncating integer mean
            __stcg(&g_acc[i], 0);                         // reset for next replay
        }
        if (threadIdx.x == 0) __stcg(&g_cnt, 0);
    }
}

extern "C" void kernel_launch(void* const* d_in, const int* in_sizes, int n_in,
                              void* d_out, int out_size) {
    const float4* x = (const float4*)d_in[0];
    float* out = (float*)d_out;
    ccl_kernel<<<N_BLK, 128>>>(x, out);
}